// round 12
// baseline (speedup 1.0000x reference)
#include <cuda_runtime.h>
#include <stdint.h>

// Problem dims (fixed by the reference)
#define D_ 8
#define B_ 16
#define E_ 2048
#define O_ 2048

#define CAP  2048           // per-batch triple-list capacity (mean ~328)
#define ZCH  8              // list chunks per batch -> 1024 blocks = 1 full wave
#define TOW  256            // threads per block / o-columns per block

// Scratch (allocation-free: __device__ globals)
// Per-batch compacted triple lists: {w_off = e*O, dm_off = (d*E+e)*O, coef, pad}
__device__ __align__(16) uint4 g_list[B_ * CAP];   // 512 KB
__device__ int   g_cnt[B_];

// ---------------------------------------------------------------------------
// Phase 1: extract active (e,d,b) triples.  One thread per (d,e).
// ---------------------------------------------------------------------------
__global__ void phase1_kernel(const float* __restrict__ Xd,
                              const float* __restrict__ Wshort,
                              const int*   __restrict__ signs_pre) {
    int t = blockIdx.x * blockDim.x + threadIdx.x;
    if (t >= D_ * E_) return;
    int d = t / E_;
    int e = t - d * E_;

    float s = (float)(2 * signs_pre[e] - 1);   // {0,1} -> {-1,+1}

    unsigned w_off  = (unsigned)(e * O_);
    unsigned dm_off = (unsigned)((d * E_ + e) * O_);

#pragma unroll
    for (int b = 0; b < B_; ++b) {
        int idx = (d * B_ + b) * E_ + e;       // (D,B,E) layout, coalesced in e
        float x = Xd[idx];                     // exactly 0.0 or 1.0
        if (x != 0.0f) {
            float coef = s * (1.0f + Wshort[idx]);
            int pos = atomicAdd(&g_cnt[b], 1);
            if (pos < CAP)
                g_list[b * CAP + pos] =
                    make_uint4(w_off, dm_off, __float_as_uint(coef), 0u);
        }
    }
}

// ---------------------------------------------------------------------------
// Phase 2: sparse stream with software-pipelined W prefetch.
//   out[b,o] += coef * W[e,o] * dmap[d,e,o]   over compacted triples
// The dmap load is predicated on w != 0 (saves ~45% dmap sectors) but w was
// fetched one 4-group earlier, so the dependency is off the critical path.
// ---------------------------------------------------------------------------
__global__ __launch_bounds__(TOW, 8)
void phase2_kernel(const float* __restrict__ W,
                   const float* __restrict__ dmap,
                   float*       __restrict__ out) {
    __shared__ __align__(16) uint4 s_ent[CAP / ZCH + 4];   // up to 256 entries

    const int o = blockIdx.x * TOW + threadIdx.x;
    const int b = blockIdx.y;
    const int z = blockIdx.z;

    int cnt = g_cnt[b];
    if (cnt > CAP) cnt = CAP;
    const int c0 = (cnt * z) / ZCH;
    const int c1 = (cnt * (z + 1)) / ZCH;
    const int n  = c1 - c0;
    if (n <= 0) return;

    // Stage this chunk's entries into SMEM (cooperative, coalesced)
    {
        const uint4* src = &g_list[b * CAP + c0];
        for (int i = threadIdx.x; i < n; i += TOW)
            s_ent[i] = src[i];
    }
    __syncthreads();

    float acc = 0.0f;
    int i = 0;

    uint4 tc[4];
    float wc[4];
    if (i + 4 <= n) {
#pragma unroll
        for (int k = 0; k < 4; ++k) {
            tc[k] = s_ent[k];
            wc[k] = __ldg(&W[tc[k].x + o]);
        }
    }

    for (; i + 4 <= n; i += 4) {
        const bool more = (i + 8 <= n);
        uint4 tn[4];
        float wn[4];
        if (more) {
#pragma unroll
            for (int k = 0; k < 4; ++k) {
                tn[k] = s_ent[i + 4 + k];
                wn[k] = __ldg(&W[tn[k].x + o]);   // prefetch next group's W
            }
        }

        // predicated dmap loads for the CURRENT group (w already resident)
        float dm[4];
#pragma unroll
        for (int k = 0; k < 4; ++k) {
            dm[k] = 0.0f;
            if (wc[k] != 0.0f) dm[k] = __ldg(&dmap[tc[k].y + o]);
        }

#pragma unroll
        for (int k = 0; k < 4; ++k)
            acc = fmaf(wc[k] * __uint_as_float(tc[k].z), dm[k], acc);

        if (more) {
#pragma unroll
            for (int k = 0; k < 4; ++k) { tc[k] = tn[k]; wc[k] = wn[k]; }
        }
    }

    // tail (< 4 triples)
    for (; i < n; ++i) {
        const uint4 t = s_ent[i];
        const float w = __ldg(&W[t.x + o]);
        float dm = 0.0f;
        if (w != 0.0f) dm = __ldg(&dmap[t.y + o]);
        acc = fmaf(w * __uint_as_float(t.z), dm, acc);
    }

    // ~41 triples/thread at 1.25% hit rate -> ~40% of lanes nonzero
    if (acc != 0.0f)
        atomicAdd(&out[b * O_ + o], acc);
}

// ---------------------------------------------------------------------------
// Launch: memset out + counters -> phase1 -> phase2. Graph-capturable.
// Input order per metadata: W, Xd, delaymap, Wshort, signs_pre.
// ---------------------------------------------------------------------------
extern "C" void kernel_launch(void* const* d_in, const int* in_sizes, int n_in,
                              void* d_out, int out_size) {
    const float* W      = (const float*)d_in[0];  // (E, O)
    const float* Xd     = (const float*)d_in[1];  // (D, B, E)
    const float* dmap   = (const float*)d_in[2];  // (D, E, O)
    const float* Wshort = (const float*)d_in[3];  // (D, B, E)
    const int*   signs  = (const int*)  d_in[4];  // (E,)
    float* out = (float*)d_out;                   // (B, O)

    cudaMemsetAsync(out, 0, (size_t)out_size * sizeof(float), 0);

    void* cnt_ptr = nullptr;
    cudaGetSymbolAddress(&cnt_ptr, g_cnt);        // host-side query, capture-safe
    cudaMemsetAsync(cnt_ptr, 0, sizeof(int) * B_, 0);

    phase1_kernel<<<(D_ * E_ + 255) / 256, 256>>>(Xd, Wshort, signs);

    dim3 grid(O_ / TOW, B_, ZCH);                 // 8 x 16 x 8 = 1024 blocks
    phase2_kernel<<<grid, TOW>>>(W, dmap, out);
}

// round 13
// speedup vs baseline: 1.4985x; 1.4985x over previous
#include <cuda_runtime.h>
#include <stdint.h>

// Problem dims (fixed by the reference)
#define D_ 8
#define B_ 16
#define E_ 2048
#define O_ 2048

#define CAP  2048           // per-batch triple-list capacity (mean ~328)
#define ZCH  16             // list chunks per batch
#define TPB  128            // phase2 threads per block
#define OV   4              // o-columns per thread (float4)

// Scratch (allocation-free: __device__ globals)
// Per-batch compacted triple lists: {w_off = e*O, dm_off = (d*E+e)*O, coef, pad}
__device__ __align__(16) uint4 g_list[B_ * CAP];   // 512 KB
__device__ int   g_cnt[B_];

// ---------------------------------------------------------------------------
// Phase 1: extract active (e,d,b) triples with block-level reservation.
// Pass 1 counts actives per batch in SMEM; ONE global atomicAdd per (block,b)
// reserves a contiguous range; pass 2 writes entries into the range.
// 64 blocks x 256 threads; one thread per (d,e).
// ---------------------------------------------------------------------------
__global__ __launch_bounds__(256)
void phase1_kernel(const float* __restrict__ Xd,
                   const float* __restrict__ Wshort,
                   const int*   __restrict__ signs_pre) {
    __shared__ int s_cnt[B_], s_base[B_], s_pos[B_];

    const int t = blockIdx.x * 256 + threadIdx.x;   // [0, 16384)
    const int d = t / E_;
    const int e = t - d * E_;

    if (threadIdx.x < B_) s_cnt[threadIdx.x] = 0;
    __syncthreads();

    // Pass 1: activity mask + per-batch counts
    unsigned m = 0u;
#pragma unroll
    for (int b = 0; b < B_; ++b) {
        float x = Xd[(d * B_ + b) * E_ + e];        // exactly 0.0 or 1.0
        if (x != 0.0f) {
            m |= (1u << b);
            atomicAdd(&s_cnt[b], 1);                // smem atomic, low contention
        }
    }
    __syncthreads();

    // Reserve contiguous global ranges: 16 global atomics per block total
    if (threadIdx.x < B_) {
        s_base[threadIdx.x] = atomicAdd(&g_cnt[threadIdx.x], s_cnt[threadIdx.x]);
        s_pos[threadIdx.x]  = 0;
    }
    __syncthreads();

    if (m == 0u) return;

    const float s = (float)(2 * signs_pre[e] - 1);  // {0,1} -> {-1,+1}
    const unsigned w_off  = (unsigned)(e * O_);
    const unsigned dm_off = (unsigned)((d * E_ + e) * O_);

    // Pass 2: write entries into reserved ranges (Wshort L2-hot)
#pragma unroll
    for (int b = 0; b < B_; ++b) {
        if ((m >> b) & 1u) {
            float coef = s * (1.0f + Wshort[(d * B_ + b) * E_ + e]);
            int pos = s_base[b] + atomicAdd(&s_pos[b], 1);
            if (pos < CAP)
                g_list[b * CAP + pos] =
                    make_uint4(w_off, dm_off, __float_as_uint(coef), 0u);
        }
    }
}

// ---------------------------------------------------------------------------
// Phase 2: sparse stream, float4 columns, software-pipelined W prefetch.
//   out[b, o..o+3] += coef * W[e, o..o+3] * dmap[d,e, o..o+3]
// Per triple: 1x LDG.128 (W) + 1 predicated LDG.128 (dmap) + 4 FMA.
// ---------------------------------------------------------------------------
__global__ __launch_bounds__(TPB, 8)
void phase2_kernel(const float* __restrict__ W,
                   const float* __restrict__ dmap,
                   float*       __restrict__ out) {
    __shared__ __align__(16) uint4 s_ent[CAP / ZCH + 2];   // up to 128 entries

    const int o = (blockIdx.x * TPB + threadIdx.x) * OV;   // 4-aligned column
    const int b = blockIdx.y;
    const int z = blockIdx.z;

    int cnt = g_cnt[b];
    if (cnt > CAP) cnt = CAP;
    const int c0 = (cnt * z) / ZCH;
    const int c1 = (cnt * (z + 1)) / ZCH;
    const int n  = c1 - c0;
    if (n <= 0) return;

    // Stage this chunk's entries into SMEM
    {
        const uint4* src = &g_list[b * CAP + c0];
        for (int i = threadIdx.x; i < n; i += TPB)
            s_ent[i] = src[i];
    }
    __syncthreads();

    float4 acc = make_float4(0.0f, 0.0f, 0.0f, 0.0f);
    int i = 0;

    // 2-group software pipeline: W for group g+1 in flight while group g's
    // predicated dmap loads + FMAs execute.
    uint4  tc[2];
    float4 wc[2];
    if (n >= 2) {
#pragma unroll
        for (int k = 0; k < 2; ++k) {
            tc[k] = s_ent[k];
            wc[k] = __ldg((const float4*)&W[tc[k].x + o]);
        }
        for (; i + 2 <= n; i += 2) {
            const bool more = (i + 4 <= n);
            uint4  tn[2];
            float4 wn[2];
            if (more) {
#pragma unroll
                for (int k = 0; k < 2; ++k) {
                    tn[k] = s_ent[i + 2 + k];
                    wn[k] = __ldg((const float4*)&W[tn[k].x + o]);  // prefetch
                }
            }

#pragma unroll
            for (int k = 0; k < 2; ++k) {
                const float4 w4 = wc[k];
                float4 dm = make_float4(0.0f, 0.0f, 0.0f, 0.0f);
                if (w4.x != 0.0f || w4.y != 0.0f || w4.z != 0.0f || w4.w != 0.0f)
                    dm = __ldg((const float4*)&dmap[tc[k].y + o]);
                const float cf = __uint_as_float(tc[k].z);
                acc.x = fmaf(w4.x * cf, dm.x, acc.x);
                acc.y = fmaf(w4.y * cf, dm.y, acc.y);
                acc.z = fmaf(w4.z * cf, dm.z, acc.z);
                acc.w = fmaf(w4.w * cf, dm.w, acc.w);
            }

            if (more) {
#pragma unroll
                for (int k = 0; k < 2; ++k) { tc[k] = tn[k]; wc[k] = wn[k]; }
            }
        }
    }

    // tail (< 2 triples)
    for (; i < n; ++i) {
        const uint4 t = s_ent[i];
        const float4 w4 = __ldg((const float4*)&W[t.x + o]);
        float4 dm = make_float4(0.0f, 0.0f, 0.0f, 0.0f);
        if (w4.x != 0.0f || w4.y != 0.0f || w4.z != 0.0f || w4.w != 0.0f)
            dm = __ldg((const float4*)&dmap[t.y + o]);
        const float cf = __uint_as_float(t.z);
        acc.x = fmaf(w4.x * cf, dm.x, acc.x);
        acc.y = fmaf(w4.y * cf, dm.y, acc.y);
        acc.z = fmaf(w4.z * cf, dm.z, acc.z);
        acc.w = fmaf(w4.w * cf, dm.w, acc.w);
    }

    // Guarded cross-chunk reduction (most accumulators are exactly zero)
    float* dst = &out[b * O_ + o];
    if (acc.x != 0.0f) atomicAdd(dst + 0, acc.x);
    if (acc.y != 0.0f) atomicAdd(dst + 1, acc.y);
    if (acc.z != 0.0f) atomicAdd(dst + 2, acc.z);
    if (acc.w != 0.0f) atomicAdd(dst + 3, acc.w);
}

// ---------------------------------------------------------------------------
// Launch: memset out + counters -> phase1 -> phase2. Graph-capturable.
// Input order per metadata: W, Xd, delaymap, Wshort, signs_pre.
// ---------------------------------------------------------------------------
extern "C" void kernel_launch(void* const* d_in, const int* in_sizes, int n_in,
                              void* d_out, int out_size) {
    const float* W      = (const float*)d_in[0];  // (E, O)
    const float* Xd     = (const float*)d_in[1];  // (D, B, E)
    const float* dmap   = (const float*)d_in[2];  // (D, E, O)
    const float* Wshort = (const float*)d_in[3];  // (D, B, E)
    const int*   signs  = (const int*)  d_in[4];  // (E,)
    float* out = (float*)d_out;                   // (B, O)

    cudaMemsetAsync(out, 0, (size_t)out_size * sizeof(float), 0);

    void* cnt_ptr = nullptr;
    cudaGetSymbolAddress(&cnt_ptr, g_cnt);        // host-side query, capture-safe
    cudaMemsetAsync(cnt_ptr, 0, sizeof(int) * B_, 0);

    phase1_kernel<<<D_ * E_ / 256, 256>>>(Xd, Wshort, signs);

    dim3 grid(O_ / (TPB * OV), B_, ZCH);          // 4 x 16 x 16 = 1024 blocks
    phase2_kernel<<<grid, TPB>>>(W, dmap, out);
}

// round 14
// speedup vs baseline: 1.6501x; 1.1011x over previous
#include <cuda_runtime.h>
#include <stdint.h>

// Problem dims (fixed by the reference)
#define D_ 8
#define B_ 16
#define E_ 2048
#define O_ 2048

#define CAP  2048           // per-batch triple capacity (mean ~328, max ~420)
#define ZCH  16             // list chunks per batch
#define TPB  128            // phase2 threads per block
#define OV   4              // o-columns per thread (float4)

// Compacted per-batch triple lists. Entry = {dm_off, coef}.
// dm_off = (d*E + e)*O;  w_off = dm_off & (E*O - 1) = dm_off & 0x3FFFFF.
__device__ __align__(8) uint2 g_list[B_ * CAP];   // 256 KB
__device__ int g_cnt[B_];

// ---------------------------------------------------------------------------
// Phase 1 (single pass): one thread per (d,e). Computes all 16 coefs in
// registers, counts actives in SMEM, reserves contiguous ranges with ONE
// global atomic per (block, b), then writes 8-byte entries.
// ---------------------------------------------------------------------------
__global__ __launch_bounds__(128)
void phase1_kernel(const float* __restrict__ Xd,
                   const float* __restrict__ Wshort,
                   const int*   __restrict__ signs_pre) {
    __shared__ int s_cnt[B_], s_base[B_], s_pos[B_];

    const int t = blockIdx.x * 128 + threadIdx.x;   // [0, 16384)
    const int d = t >> 11;
    const int e = t & (E_ - 1);

    if (threadIdx.x < B_) s_cnt[threadIdx.x] = 0;
    __syncthreads();

    const float s = (float)(2 * signs_pre[e] - 1);  // {0,1} -> {-1,+1}

    unsigned m = 0u;
    float c[B_];
#pragma unroll
    for (int b = 0; b < B_; ++b) {
        int idx = (d * B_ + b) * E_ + e;            // coalesced over e per b
        float x  = Xd[idx];                         // exactly 0.0 or 1.0
        c[b] = s * (1.0f + Wshort[idx]);
        if (x != 0.0f) {
            m |= (1u << b);
            atomicAdd(&s_cnt[b], 1);
        }
    }
    __syncthreads();

    if (threadIdx.x < B_) {
        s_base[threadIdx.x] = atomicAdd(&g_cnt[threadIdx.x], s_cnt[threadIdx.x]);
        s_pos[threadIdx.x]  = 0;
    }
    __syncthreads();

    if (m == 0u) return;

    const unsigned dm_off = (unsigned)((d * E_ + e) * O_);
#pragma unroll
    for (int b = 0; b < B_; ++b) {
        if ((m >> b) & 1u) {
            int pos = s_base[b] + atomicAdd(&s_pos[b], 1);
            if (pos < CAP)
                g_list[b * CAP + pos] = make_uint2(dm_off, __float_as_uint(c[b]));
        }
    }
}

// ---------------------------------------------------------------------------
// Phase 2: sparse stream, float4 columns, 3-stage software pipeline:
//   stage i+2: W prefetch        (LDG.128)
//   stage i+1: predicated dmap   (LDG.128, predicate from already-resident W)
//   stage i  : 4x FMA consume
// ---------------------------------------------------------------------------
__device__ __forceinline__ bool nz4(const float4 v) {
    return (__float_as_uint(v.x) | __float_as_uint(v.y) |
            __float_as_uint(v.z) | __float_as_uint(v.w)) != 0u;
}

__global__ __launch_bounds__(TPB, 8)
void phase2_kernel(const float* __restrict__ W,
                   const float* __restrict__ dmap,
                   float*       __restrict__ out) {
    __shared__ __align__(8) uint2 s_ent[CAP / ZCH + 2];   // up to 128 entries

    const int o = (blockIdx.x * TPB + threadIdx.x) * OV;  // 16B-aligned column
    const int b = blockIdx.y;
    const int z = blockIdx.z;

    int cnt = g_cnt[b];
    if (cnt > CAP) cnt = CAP;
    const int c0 = (cnt * z) / ZCH;
    const int c1 = (cnt * (z + 1)) / ZCH;
    const int n  = c1 - c0;
    if (n <= 0) return;

    {
        const uint2* src = &g_list[b * CAP + c0];
        for (int i = threadIdx.x; i < n; i += TPB)
            s_ent[i] = src[i];
    }
    __syncthreads();

    const float4 z4 = make_float4(0.0f, 0.0f, 0.0f, 0.0f);
    float4 acc = z4;

    if (n >= 2) {
        uint2  e0 = s_ent[0];
        uint2  e1 = s_ent[1];
        float4 w0 = __ldg((const float4*)&W[(e0.x & 0x3FFFFFu) + o]);
        float4 w1 = __ldg((const float4*)&W[(e1.x & 0x3FFFFFu) + o]);
        float4 d0 = z4;
        if (nz4(w0)) d0 = __ldg((const float4*)&dmap[e0.x + o]);

        for (int i = 0; i + 2 < n; ++i) {
            // stage i+2: W prefetch
            const uint2  e2 = s_ent[i + 2];
            const float4 w2 = __ldg((const float4*)&W[(e2.x & 0x3FFFFFu) + o]);
            // stage i+1: predicated dmap prefetch (w1 resident since i-1)
            float4 d1 = z4;
            if (nz4(w1)) d1 = __ldg((const float4*)&dmap[e1.x + o]);
            // stage i: consume
            const float cf = __uint_as_float(e0.y);
            acc.x = fmaf(w0.x * cf, d0.x, acc.x);
            acc.y = fmaf(w0.y * cf, d0.y, acc.y);
            acc.z = fmaf(w0.z * cf, d0.z, acc.z);
            acc.w = fmaf(w0.w * cf, d0.w, acc.w);
            // rotate
            e0 = e1; w0 = w1; d0 = d1;
            e1 = e2; w1 = w2;
        }
        // epilog: e0 (dmap resident) and e1 (needs dmap)
        float4 d1 = z4;
        if (nz4(w1)) d1 = __ldg((const float4*)&dmap[e1.x + o]);
        const float cf0 = __uint_as_float(e0.y);
        const float cf1 = __uint_as_float(e1.y);
        acc.x = fmaf(w0.x * cf0, d0.x, acc.x);
        acc.y = fmaf(w0.y * cf0, d0.y, acc.y);
        acc.z = fmaf(w0.z * cf0, d0.z, acc.z);
        acc.w = fmaf(w0.w * cf0, d0.w, acc.w);
        acc.x = fmaf(w1.x * cf1, d1.x, acc.x);
        acc.y = fmaf(w1.y * cf1, d1.y, acc.y);
        acc.z = fmaf(w1.z * cf1, d1.z, acc.z);
        acc.w = fmaf(w1.w * cf1, d1.w, acc.w);
    } else {  // n == 1
        const uint2  e0 = s_ent[0];
        const float4 w0 = __ldg((const float4*)&W[(e0.x & 0x3FFFFFu) + o]);
        float4 d0 = z4;
        if (nz4(w0)) d0 = __ldg((const float4*)&dmap[e0.x + o]);
        const float cf = __uint_as_float(e0.y);
        acc.x = fmaf(w0.x * cf, d0.x, acc.x);
        acc.y = fmaf(w0.y * cf, d0.y, acc.y);
        acc.z = fmaf(w0.z * cf, d0.z, acc.z);
        acc.w = fmaf(w0.w * cf, d0.w, acc.w);
    }

    // Guarded cross-chunk reduction
    float* dst = &out[b * O_ + o];
    if (acc.x != 0.0f) atomicAdd(dst + 0, acc.x);
    if (acc.y != 0.0f) atomicAdd(dst + 1, acc.y);
    if (acc.z != 0.0f) atomicAdd(dst + 2, acc.z);
    if (acc.w != 0.0f) atomicAdd(dst + 3, acc.w);
}

// ---------------------------------------------------------------------------
// Launch: memset out + counters -> phase1 -> phase2. Graph-capturable.
// Input order per metadata: W, Xd, delaymap, Wshort, signs_pre.
// ---------------------------------------------------------------------------
extern "C" void kernel_launch(void* const* d_in, const int* in_sizes, int n_in,
                              void* d_out, int out_size) {
    const float* W      = (const float*)d_in[0];  // (E, O)
    const float* Xd     = (const float*)d_in[1];  // (D, B, E)
    const float* dmap   = (const float*)d_in[2];  // (D, E, O)
    const float* Wshort = (const float*)d_in[3];  // (D, B, E)
    const int*   signs  = (const int*)  d_in[4];  // (E,)
    float* out = (float*)d_out;                   // (B, O)

    cudaMemsetAsync(out, 0, (size_t)out_size * sizeof(float), 0);

    void* cnt_ptr = nullptr;
    cudaGetSymbolAddress(&cnt_ptr, g_cnt);        // host-side query, capture-safe
    cudaMemsetAsync(cnt_ptr, 0, sizeof(int) * B_, 0);

    phase1_kernel<<<D_ * E_ / 128, 128>>>(Xd, Wshort, signs);

    dim3 grid(O_ / (TPB * OV), B_, ZCH);          // 4 x 16 x 16 = 1024 blocks
    phase2_kernel<<<grid, TPB>>>(W, dmap, out);
}